// round 6
// baseline (speedup 1.0000x reference)
#include <cuda_runtime.h>
#include <math.h>

// VanillaRNN persistent kernel, v3:
//  - hT kept transposed in gmem; 512 threads/CTA, k split 4 ways (latency hiding)
//  - fma.rn.f32x2 packed math, 8x2 microtile per thread
//  - all-thread reduction + epilogue (4 tanh/thread), x[:,t] staged once to smem

#define GX 16      // column blocks (512 / 32)
#define GY 8       // row blocks    (512 / 64)
#define NCTA (GX*GY)
#define NTHR 512

constexpr int Bsz = 512, S = 1024, H = 512, OUTD = 10;
constexpr int BM = 64, BN = 32;
constexpr int KH = 4;                  // k-way split
constexpr int KPH = H / KH;            // 128 k per group
constexpr int KC = 32;                 // k per chunk per group
constexpr int NCHUNK = KPH / KC;       // 4
constexpr int WS_STRIDE = 34;
constexpr int HS_STRIDE = 68;
constexpr int WS_FLOATS = H * WS_STRIDE;                  // 17408
constexpr int HS_BUF = KH * KC * HS_STRIDE;               // 8704 floats per buffer
constexpr int HS_FLOATS = 2 * HS_BUF;                     // 17408
constexpr int SMEM_BYTES = (WS_FLOATS + HS_FLOATS) * 4;   // 139264 B

__device__ __align__(16) float g_hT[2][H * Bsz];
__device__ unsigned g_arrive = 0;
__device__ unsigned g_phase  = 0;

__device__ __forceinline__ void grid_barrier(unsigned v) {
    __syncthreads();
    if (threadIdx.x == 0) {
        __threadfence();
        unsigned prev = atomicAdd(&g_arrive, 1u);
        if (prev == (unsigned)(NCTA - 1)) {
            *(volatile unsigned*)&g_arrive = 0u;
            __threadfence();
            *(volatile unsigned*)&g_phase = v;
        } else {
            while (*(volatile unsigned*)&g_phase != v) { }
        }
        __threadfence();
    }
    __syncthreads();
}

__global__ void __launch_bounds__(NTHR, 1)
rnn_kernel(const float* __restrict__ x,    const float* __restrict__ W_hx,
           const float* __restrict__ b_hx, const float* __restrict__ W_hh,
           const float* __restrict__ b_hh, const float* __restrict__ W_oh,
           const float* __restrict__ b_oh, float* __restrict__ out)
{
    extern __shared__ float sm[];
    float* ws = sm;                       // ws[k*34 + jl] = W_hh[(col0+jl)][k]
    float* hs = sm + WS_FLOATS;           // hs[buf][kh][kl][r]
    float* part = hs;                     // 8192-float partial scratch (aliases buf0)
    float* xs   = hs + 8192;              // 64 floats x[:,t] (still inside buf0 span)
    const unsigned hs_u32 = (unsigned)__cvta_generic_to_shared(hs);

    const int tid  = threadIdx.x;
    const int cb   = blockIdx.x;
    const int rb   = blockIdx.y;
    const int row0 = rb * BM;
    const int col0 = cb * BN;
    // compute roles: k-group, 2 cols, 8 rows
    const int kh = tid >> 7;              // 0..3
    const int cg = tid & 15;              // cols col0 + 2cg + {0,1}
    const int rg = (tid >> 4) & 7;        // rows row0 + 8rg + {0..7}
    // staging roles
    const int rf = tid & 15;              // float4 index along 64 rows
    const int kr = tid >> 4;              // 0..31, k-row base (adds 32*i)
    // epilogue roles: column jj, row quad rr
    const int jj = tid >> 4;              // 0..31
    const int rr = tid & 15;              // rows row0 + 4rr + {0..3}

    // W_hh tile (constant over all steps), transposed + padded.
    for (int idx = tid; idx < BN * H; idx += NTHR) {
        int jl = idx >> 9, k = idx & (H - 1);
        ws[k * WS_STRIDE + jl] = W_hh[(col0 + jl) * H + k];
    }
    const float wxj = W_hx[col0 + jj];
    const float bbj = b_hx[col0 + jj] + b_hh[col0 + jj];
    // h0 = zeros (transposed layout)
    for (int idx = tid; idx < BN * BM; idx += NTHR) {
        int jl = idx >> 6, rl = idx & 63;
        g_hT[0][(col0 + jl) * Bsz + row0 + rl] = 0.0f;
    }
    grid_barrier(1u);

    const unsigned hk_u = hs_u32 + ((unsigned)(kh * (KC * HS_STRIDE)) + (unsigned)(rg * 8)) * 4u;

    for (int t = 0; t < S; ++t) {
        const float* hin  = g_hT[t & 1];
        float*       hout = g_hT[(t + 1) & 1];

        // stage chunk 0 -> buf 0 (all 4 k-groups)
        float4 pf[4];
        #pragma unroll
        for (int i = 0; i < 4; ++i) {
            int krow = kr + i * 32;               // 0..127
            int half = krow >> 5, kl = krow & 31;
            int kg = half * KPH + kl;
            pf[i] = *(const float4*)(hin + kg * Bsz + row0 + rf * 4);
        }
        #pragma unroll
        for (int i = 0; i < 4; ++i) {
            int krow = kr + i * 32;
            int half = krow >> 5, kl = krow & 31;
            *(float4*)(hs + half * (KC * HS_STRIDE) + kl * HS_STRIDE + rf * 4) = pf[i];
        }

        unsigned long long a0[4] = {0,0,0,0}, a1[4] = {0,0,0,0};

        #pragma unroll 1
        for (int c = 0; c < NCHUNK; ++c) {
            __syncthreads();              // chunk c visible in buf c&1
            if (c + 1 < NCHUNK) {         // prefetch next chunk from L2
                #pragma unroll
                for (int i = 0; i < 4; ++i) {
                    int krow = kr + i * 32;
                    int half = krow >> 5, kl = krow & 31;
                    int kg = half * KPH + (c + 1) * KC + kl;
                    pf[i] = *(const float4*)(hin + kg * Bsz + row0 + rf * 4);
                }
            }
            const float* wk = ws + (kh * KPH + c * KC) * WS_STRIDE + 2 * cg;
            const unsigned hb = hk_u + (unsigned)((c & 1) * HS_BUF) * 4u;
            #pragma unroll 8
            for (int kk = 0; kk < KC; ++kk) {
                float2 wv = *(const float2*)(wk + kk * WS_STRIDE);
                unsigned long long w0, w1, h01, h23, h45, h67;
                asm("mov.b64 %0,{%1,%1};" : "=l"(w0) : "f"(wv.x));
                asm("mov.b64 %0,{%1,%1};" : "=l"(w1) : "f"(wv.y));
                unsigned a = hb + (unsigned)(kk * HS_STRIDE) * 4u;
                asm volatile("ld.shared.v2.u64 {%0,%1},[%2];" : "=l"(h01), "=l"(h23) : "r"(a));
                asm volatile("ld.shared.v2.u64 {%0,%1},[%2];" : "=l"(h45), "=l"(h67) : "r"(a + 16));
                asm("fma.rn.f32x2 %0,%1,%2,%0;" : "+l"(a0[0]) : "l"(h01), "l"(w0));
                asm("fma.rn.f32x2 %0,%1,%2,%0;" : "+l"(a1[0]) : "l"(h01), "l"(w1));
                asm("fma.rn.f32x2 %0,%1,%2,%0;" : "+l"(a0[1]) : "l"(h23), "l"(w0));
                asm("fma.rn.f32x2 %0,%1,%2,%0;" : "+l"(a1[1]) : "l"(h23), "l"(w1));
                asm("fma.rn.f32x2 %0,%1,%2,%0;" : "+l"(a0[2]) : "l"(h45), "l"(w0));
                asm("fma.rn.f32x2 %0,%1,%2,%0;" : "+l"(a1[2]) : "l"(h45), "l"(w1));
                asm("fma.rn.f32x2 %0,%1,%2,%0;" : "+l"(a0[3]) : "l"(h67), "l"(w0));
                asm("fma.rn.f32x2 %0,%1,%2,%0;" : "+l"(a1[3]) : "l"(h67), "l"(w1));
            }
            if (c + 1 < NCHUNK) {
                __syncthreads();          // buf (c+1)&1 free (last read 2 chunks ago)
                float* dst = hs + ((c + 1) & 1) * HS_BUF;
                #pragma unroll
                for (int i = 0; i < 4; ++i) {
                    int krow = kr + i * 32;
                    int half = krow >> 5, kl = krow & 31;
                    *(float4*)(dst + half * (KC * HS_STRIDE) + kl * HS_STRIDE + rf * 4) = pf[i];
                }
            }
        }
        // All threads are past reading buf0 (top-of-chunk-3 sync); chunk 3 reads buf1.
        // Write 16 partials into buf0-aliased scratch: part[((kh*16+cg)*8+rg)*16 + c01*8 + j]
        {
            unsigned long long* pb = (unsigned long long*)(part + ((kh * 16 + cg) * 8 + rg) * 16);
            asm volatile("st.shared.v2.u64 [%0],{%1,%2};" ::
                         "l"(pb),     "l"(a0[0]), "l"(a0[1]) : "memory");
            asm volatile("st.shared.v2.u64 [%0],{%1,%2};" ::
                         "l"(pb + 2), "l"(a0[2]), "l"(a0[3]) : "memory");
            asm volatile("st.shared.v2.u64 [%0],{%1,%2};" ::
                         "l"(pb + 4), "l"(a1[0]), "l"(a1[1]) : "memory");
            asm volatile("st.shared.v2.u64 [%0],{%1,%2};" ::
                         "l"(pb + 6), "l"(a1[2]), "l"(a1[3]) : "memory");
        }
        if (tid < BM) xs[tid] = x[(row0 + tid) * S + t];
        __syncthreads();

        // Epilogue: every thread finishes 4 outputs (col jj, rows 4rr..4rr+3)
        {
            float4 acc = make_float4(0.f, 0.f, 0.f, 0.f);
            #pragma unroll
            for (int k4 = 0; k4 < KH; ++k4) {
                float4 p4 = *(const float4*)(part
                              + ((k4 * 16 + (jj >> 1)) * 8 + (rr >> 1)) * 16
                              + (jj & 1) * 8 + (rr & 1) * 4);
                acc.x += p4.x; acc.y += p4.y; acc.z += p4.z; acc.w += p4.w;
            }
            float4 xv = *(const float4*)(xs + rr * 4);
            acc.x = tanhf(acc.x + xv.x * wxj + bbj);
            acc.y = tanhf(acc.y + xv.y * wxj + bbj);
            acc.z = tanhf(acc.z + xv.z * wxj + bbj);
            acc.w = tanhf(acc.w + xv.w * wxj + bbj);
            *(float4*)(hout + (col0 + jj) * Bsz + row0 + rr * 4) = acc;
        }
        grid_barrier(t == S - 1 ? 0u : (unsigned)(t + 2));
    }

    // Final projection + softmax (col-block-0 CTAs, 64 rows each). hT final in buf 0.
    if (cb == 0) {
        for (int idx = tid; idx < OUTD * H; idx += NTHR) sm[idx] = W_oh[idx];
        __syncthreads();
        const float* hT = g_hT[0];
        int r = tid & 63, g = tid >> 6;           // 8 c-groups of 64
        float p[OUTD];
        #pragma unroll
        for (int od = 0; od < OUTD; ++od) p[od] = 0.f;
        for (int c2 = g * 64; c2 < g * 64 + 64; ++c2) {
            float hv = hT[c2 * Bsz + row0 + r];
            #pragma unroll
            for (int od = 0; od < OUTD; ++od) p[od] += hv * sm[od * H + c2];
        }
        float* pr = sm + OUTD * H;
        #pragma unroll
        for (int od = 0; od < OUTD; ++od) pr[tid * OUTD + od] = p[od];
        __syncthreads();
        if (tid < 64) {
            float o[OUTD];
            #pragma unroll
            for (int od = 0; od < OUTD; ++od) {
                float s0 = 0.f;
                #pragma unroll
                for (int g2 = 0; g2 < 8; ++g2)
                    s0 += pr[(g2 * 64 + tid) * OUTD + od];
                o[od] = s0 + b_oh[od];
            }
            float m = o[0];
            #pragma unroll
            for (int od = 1; od < OUTD; ++od) m = fmaxf(m, o[od]);
            float ssum = 0.f;
            #pragma unroll
            for (int od = 0; od < OUTD; ++od) { o[od] = expf(o[od] - m); ssum += o[od]; }
            float inv = 1.0f / ssum;
            #pragma unroll
            for (int od = 0; od < OUTD; ++od)
                out[(row0 + tid) * OUTD + od] = o[od] * inv;
        }
    }
}

extern "C" void kernel_launch(void* const* d_in, const int* in_sizes, int n_in,
                              void* d_out, int out_size) {
    const float* x    = (const float*)d_in[0];
    const float* W_hx = (const float*)d_in[1];
    const float* b_hx = (const float*)d_in[2];
    const float* W_hh = (const float*)d_in[3];
    const float* b_hh = (const float*)d_in[4];
    const float* W_oh = (const float*)d_in[5];
    const float* b_oh = (const float*)d_in[6];
    float* out = (float*)d_out;

    cudaFuncSetAttribute(rnn_kernel, cudaFuncAttributeMaxDynamicSharedMemorySize, SMEM_BYTES);
    rnn_kernel<<<dim3(GX, GY, 1), NTHR, SMEM_BYTES>>>(x, W_hx, b_hx, W_hh, b_hh, W_oh, b_oh, out);
}

// round 7
// speedup vs baseline: 1.0494x; 1.0494x over previous
#include <cuda_runtime.h>
#include <math.h>

// VanillaRNN persistent kernel, v3:
//  - hT kept transposed in gmem; 512 threads/CTA, k split 4 ways (latency hiding)
//  - fma.rn.f32x2 packed math, 8x2 microtile per thread
//  - all-thread reduction + epilogue (4 tanh/thread), x[:,t] staged once to smem

#define GX 16      // column blocks (512 / 32)
#define GY 8       // row blocks    (512 / 64)
#define NCTA (GX*GY)
#define NTHR 512

constexpr int Bsz = 512, S = 1024, H = 512, OUTD = 10;
constexpr int BM = 64, BN = 32;
constexpr int KH = 4;                  // k-way split
constexpr int KPH = H / KH;            // 128 k per group
constexpr int KC = 32;                 // k per chunk per group
constexpr int NCHUNK = KPH / KC;       // 4
constexpr int WS_STRIDE = 34;
constexpr int HS_STRIDE = 68;
constexpr int WS_FLOATS = H * WS_STRIDE;                  // 17408
constexpr int HS_BUF = KH * KC * HS_STRIDE;               // 8704 floats per buffer
constexpr int HS_FLOATS = 2 * HS_BUF;                     // 17408
constexpr int SMEM_BYTES = (WS_FLOATS + HS_FLOATS) * 4;   // 139264 B

__device__ __align__(16) float g_hT[2][H * Bsz];
__device__ unsigned g_arrive = 0;
__device__ unsigned g_phase  = 0;

__device__ __forceinline__ void grid_barrier(unsigned v) {
    __syncthreads();
    if (threadIdx.x == 0) {
        __threadfence();
        unsigned prev = atomicAdd(&g_arrive, 1u);
        if (prev == (unsigned)(NCTA - 1)) {
            *(volatile unsigned*)&g_arrive = 0u;
            __threadfence();
            *(volatile unsigned*)&g_phase = v;
        } else {
            while (*(volatile unsigned*)&g_phase != v) { }
        }
        __threadfence();
    }
    __syncthreads();
}

__global__ void __launch_bounds__(NTHR, 1)
rnn_kernel(const float* __restrict__ x,    const float* __restrict__ W_hx,
           const float* __restrict__ b_hx, const float* __restrict__ W_hh,
           const float* __restrict__ b_hh, const float* __restrict__ W_oh,
           const float* __restrict__ b_oh, float* __restrict__ out)
{
    extern __shared__ float sm[];
    float* ws = sm;                       // ws[k*34 + jl] = W_hh[(col0+jl)][k]
    float* hs = sm + WS_FLOATS;           // hs[buf][kh][kl][r]
    float* part = hs;                     // 8192-float partial scratch (aliases buf0)
    float* xs   = hs + 8192;              // 64 floats x[:,t] (still inside buf0 span)
    const unsigned hs_u32 = (unsigned)__cvta_generic_to_shared(hs);

    const int tid  = threadIdx.x;
    const int cb   = blockIdx.x;
    const int rb   = blockIdx.y;
    const int row0 = rb * BM;
    const int col0 = cb * BN;
    // compute roles: k-group, 2 cols, 8 rows
    const int kh = tid >> 7;              // 0..3
    const int cg = tid & 15;              // cols col0 + 2cg + {0,1}
    const int rg = (tid >> 4) & 7;        // rows row0 + 8rg + {0..7}
    // staging roles
    const int rf = tid & 15;              // float4 index along 64 rows
    const int kr = tid >> 4;              // 0..31, k-row base (adds 32*i)
    // epilogue roles: column jj, row quad rr
    const int jj = tid >> 4;              // 0..31
    const int rr = tid & 15;              // rows row0 + 4rr + {0..3}

    // W_hh tile (constant over all steps), transposed + padded.
    for (int idx = tid; idx < BN * H; idx += NTHR) {
        int jl = idx >> 9, k = idx & (H - 1);
        ws[k * WS_STRIDE + jl] = W_hh[(col0 + jl) * H + k];
    }
    const float wxj = W_hx[col0 + jj];
    const float bbj = b_hx[col0 + jj] + b_hh[col0 + jj];
    // h0 = zeros (transposed layout)
    for (int idx = tid; idx < BN * BM; idx += NTHR) {
        int jl = idx >> 6, rl = idx & 63;
        g_hT[0][(col0 + jl) * Bsz + row0 + rl] = 0.0f;
    }
    grid_barrier(1u);

    const unsigned hk_u = hs_u32 + ((unsigned)(kh * (KC * HS_STRIDE)) + (unsigned)(rg * 8)) * 4u;

    for (int t = 0; t < S; ++t) {
        const float* hin  = g_hT[t & 1];
        float*       hout = g_hT[(t + 1) & 1];

        // stage chunk 0 -> buf 0 (all 4 k-groups)
        float4 pf[4];
        #pragma unroll
        for (int i = 0; i < 4; ++i) {
            int krow = kr + i * 32;               // 0..127
            int half = krow >> 5, kl = krow & 31;
            int kg = half * KPH + kl;
            pf[i] = *(const float4*)(hin + kg * Bsz + row0 + rf * 4);
        }
        #pragma unroll
        for (int i = 0; i < 4; ++i) {
            int krow = kr + i * 32;
            int half = krow >> 5, kl = krow & 31;
            *(float4*)(hs + half * (KC * HS_STRIDE) + kl * HS_STRIDE + rf * 4) = pf[i];
        }

        unsigned long long a0[4] = {0,0,0,0}, a1[4] = {0,0,0,0};

        #pragma unroll 1
        for (int c = 0; c < NCHUNK; ++c) {
            __syncthreads();              // chunk c visible in buf c&1
            if (c + 1 < NCHUNK) {         // prefetch next chunk from L2
                #pragma unroll
                for (int i = 0; i < 4; ++i) {
                    int krow = kr + i * 32;
                    int half = krow >> 5, kl = krow & 31;
                    int kg = half * KPH + (c + 1) * KC + kl;
                    pf[i] = *(const float4*)(hin + kg * Bsz + row0 + rf * 4);
                }
            }
            const float* wk = ws + (kh * KPH + c * KC) * WS_STRIDE + 2 * cg;
            const unsigned hb = hk_u + (unsigned)((c & 1) * HS_BUF) * 4u;
            #pragma unroll 8
            for (int kk = 0; kk < KC; ++kk) {
                float2 wv = *(const float2*)(wk + kk * WS_STRIDE);
                unsigned long long w0, w1, h01, h23, h45, h67;
                asm("mov.b64 %0,{%1,%1};" : "=l"(w0) : "f"(wv.x));
                asm("mov.b64 %0,{%1,%1};" : "=l"(w1) : "f"(wv.y));
                unsigned a = hb + (unsigned)(kk * HS_STRIDE) * 4u;
                asm volatile("ld.shared.v2.u64 {%0,%1},[%2];" : "=l"(h01), "=l"(h23) : "r"(a));
                asm volatile("ld.shared.v2.u64 {%0,%1},[%2];" : "=l"(h45), "=l"(h67) : "r"(a + 16));
                asm("fma.rn.f32x2 %0,%1,%2,%0;" : "+l"(a0[0]) : "l"(h01), "l"(w0));
                asm("fma.rn.f32x2 %0,%1,%2,%0;" : "+l"(a1[0]) : "l"(h01), "l"(w1));
                asm("fma.rn.f32x2 %0,%1,%2,%0;" : "+l"(a0[1]) : "l"(h23), "l"(w0));
                asm("fma.rn.f32x2 %0,%1,%2,%0;" : "+l"(a1[1]) : "l"(h23), "l"(w1));
                asm("fma.rn.f32x2 %0,%1,%2,%0;" : "+l"(a0[2]) : "l"(h45), "l"(w0));
                asm("fma.rn.f32x2 %0,%1,%2,%0;" : "+l"(a1[2]) : "l"(h45), "l"(w1));
                asm("fma.rn.f32x2 %0,%1,%2,%0;" : "+l"(a0[3]) : "l"(h67), "l"(w0));
                asm("fma.rn.f32x2 %0,%1,%2,%0;" : "+l"(a1[3]) : "l"(h67), "l"(w1));
            }
            if (c + 1 < NCHUNK) {
                __syncthreads();          // buf (c+1)&1 free (last read 2 chunks ago)
                float* dst = hs + ((c + 1) & 1) * HS_BUF;
                #pragma unroll
                for (int i = 0; i < 4; ++i) {
                    int krow = kr + i * 32;
                    int half = krow >> 5, kl = krow & 31;
                    *(float4*)(dst + half * (KC * HS_STRIDE) + kl * HS_STRIDE + rf * 4) = pf[i];
                }
            }
        }
        // All threads are past reading buf0 (top-of-chunk-3 sync); chunk 3 reads buf1.
        // Write 16 partials into buf0-aliased scratch: part[((kh*16+cg)*8+rg)*16 + c01*8 + j]
        {
            unsigned long long* pb = (unsigned long long*)(part + ((kh * 16 + cg) * 8 + rg) * 16);
            asm volatile("st.shared.v2.u64 [%0],{%1,%2};" ::
                         "l"(pb),     "l"(a0[0]), "l"(a0[1]) : "memory");
            asm volatile("st.shared.v2.u64 [%0],{%1,%2};" ::
                         "l"(pb + 2), "l"(a0[2]), "l"(a0[3]) : "memory");
            asm volatile("st.shared.v2.u64 [%0],{%1,%2};" ::
                         "l"(pb + 4), "l"(a1[0]), "l"(a1[1]) : "memory");
            asm volatile("st.shared.v2.u64 [%0],{%1,%2};" ::
                         "l"(pb + 6), "l"(a1[2]), "l"(a1[3]) : "memory");
        }
        if (tid < BM) xs[tid] = x[(row0 + tid) * S + t];
        __syncthreads();

        // Epilogue: every thread finishes 4 outputs (col jj, rows 4rr..4rr+3)
        {
            float4 acc = make_float4(0.f, 0.f, 0.f, 0.f);
            #pragma unroll
            for (int k4 = 0; k4 < KH; ++k4) {
                float4 p4 = *(const float4*)(part
                              + ((k4 * 16 + (jj >> 1)) * 8 + (rr >> 1)) * 16
                              + (jj & 1) * 8 + (rr & 1) * 4);
                acc.x += p4.x; acc.y += p4.y; acc.z += p4.z; acc.w += p4.w;
            }
            float4 xv = *(const float4*)(xs + rr * 4);
            acc.x = tanhf(acc.x + xv.x * wxj + bbj);
            acc.y = tanhf(acc.y + xv.y * wxj + bbj);
            acc.z = tanhf(acc.z + xv.z * wxj + bbj);
            acc.w = tanhf(acc.w + xv.w * wxj + bbj);
            *(float4*)(hout + (col0 + jj) * Bsz + row0 + rr * 4) = acc;
        }
        grid_barrier(t == S - 1 ? 0u : (unsigned)(t + 2));
    }

    // Final projection + softmax (col-block-0 CTAs, 64 rows each). hT final in buf 0.
    if (cb == 0) {
        for (int idx = tid; idx < OUTD * H; idx += NTHR) sm[idx] = W_oh[idx];
        __syncthreads();
        const float* hT = g_hT[0];
        int r = tid & 63, g = tid >> 6;           // 8 c-groups of 64
        float p[OUTD];
        #pragma unroll
        for (int od = 0; od < OUTD; ++od) p[od] = 0.f;
        for (int c2 = g * 64; c2 < g * 64 + 64; ++c2) {
            float hv = hT[c2 * Bsz + row0 + r];
            #pragma unroll
            for (int od = 0; od < OUTD; ++od) p[od] += hv * sm[od * H + c2];
        }
        float* pr = sm + OUTD * H;
        #pragma unroll
        for (int od = 0; od < OUTD; ++od) pr[tid * OUTD + od] = p[od];
        __syncthreads();
        if (tid < 64) {
            float o[OUTD];
            #pragma unroll
            for (int od = 0; od < OUTD; ++od) {
                float s0 = 0.f;
                #pragma unroll
                for (int g2 = 0; g2 < 8; ++g2)
                    s0 += pr[(g2 * 64 + tid) * OUTD + od];
                o[od] = s0 + b_oh[od];
            }
            float m = o[0];
            #pragma unroll
            for (int od = 1; od < OUTD; ++od) m = fmaxf(m, o[od]);
            float ssum = 0.f;
            #pragma unroll
            for (int od = 0; od < OUTD; ++od) { o[od] = expf(o[od] - m); ssum += o[od]; }
            float inv = 1.0f / ssum;
            #pragma unroll
            for (int od = 0; od < OUTD; ++od)
                out[(row0 + tid) * OUTD + od] = o[od] * inv;
        }
    }
}

extern "C" void kernel_launch(void* const* d_in, const int* in_sizes, int n_in,
                              void* d_out, int out_size) {
    const float* x    = (const float*)d_in[0];
    const float* W_hx = (const float*)d_in[1];
    const float* b_hx = (const float*)d_in[2];
    const float* W_hh = (const float*)d_in[3];
    const float* b_hh = (const float*)d_in[4];
    const float* W_oh = (const float*)d_in[5];
    const float* b_oh = (const float*)d_in[6];
    float* out = (float*)d_out;

    cudaFuncSetAttribute(rnn_kernel, cudaFuncAttributeMaxDynamicSharedMemorySize, SMEM_BYTES);
    rnn_kernel<<<dim3(GX, GY, 1), NTHR, SMEM_BYTES>>>(x, W_hx, b_hx, W_hh, b_hh, W_oh, b_oh, out);
}

// round 10
// speedup vs baseline: 1.3348x; 1.2719x over previous
#include <cuda_runtime.h>
#include <math.h>
#include <stdint.h>

// VanillaRNN persistent kernel, v5: warp-level mma.sync TF32 3-product split.
// (tcgen05 is not reachable: harness compiles via compute_103 virtual target.)
// 128 CTAs, CTA tile 64(batch) x 32(cols), K=512 split 8 ways across warps.
// B (W_hh hi/lo tf32) fragment-ready in smem, built ONCE, resident all steps.
// A (h) staged per 64-k chunk, hi/lo split on the fly, double buffered.
// Per-step cross-warp D reduction through smem, tanh epilogue, grid barrier.

#define CBX 16     // column blocks (512/32)
#define RBY 8      // row blocks    (512/64)
#define NCTA (CBX*RBY)
#define NTHR 256

constexpr int S = 1024, H = 512, OUTD = 10;
constexpr int BM = 64, BN = 32;
constexpr int NCH = 8;                       // 512/64 k-chunks

// smem byte offsets
constexpr int SM_XS = 0;                     // 64 floats x[:,t]
constexpr int SM_WX = 256;                   // 32 floats W_hx
constexpr int SM_BB = 384;                   // 32 floats b_hx+b_hh
constexpr int SM_A  = 1024;                  // A: [2 buf][2 plane][64 rows][68]
constexpr int A_PLANE = 64 * 68 * 4;         // 17408 B
constexpr int A_BUF   = 2 * A_PLANE;         // 34816 B
constexpr int SM_B  = SM_A + 2 * A_BUF;      // 70656
constexpr int B_PLANE = 64 * 2 * 32 * 16;    // 65536 B (64 kb x 2 np x 32 lanes x f4)
constexpr int SMEM_BYTES = SM_B + 2 * B_PLANE;   // 201728 B

__device__ __align__(16) float g_h[2][H * H];    // ping-pong hidden state (row-major)
__device__ unsigned g_arrive = 0;
__device__ unsigned g_phase  = 0;

__device__ __forceinline__ void grid_barrier(unsigned v) {
    __syncthreads();
    if (threadIdx.x == 0) {
        __threadfence();
        unsigned prev = atomicAdd(&g_arrive, 1u);
        if (prev == (unsigned)(NCTA - 1)) {
            *(volatile unsigned*)&g_arrive = 0u;
            __threadfence();
            *(volatile unsigned*)&g_phase = v;
        } else {
            while (*(volatile unsigned*)&g_phase != v) { }
        }
        __threadfence();
    }
    __syncthreads();
}

__device__ __forceinline__ float tf32_rna(float v) {
    float r; asm("cvt.rna.tf32.f32 %0, %1;" : "=f"(r) : "f"(v)); return r;
}
__device__ __forceinline__ uint32_t fu(float v) { return __float_as_uint(v); }

__device__ __forceinline__ void mma8(float d[4], uint32_t a0, uint32_t a1,
                                     uint32_t a2, uint32_t a3,
                                     uint32_t b0, uint32_t b1) {
    asm volatile(
        "mma.sync.aligned.m16n8k8.row.col.f32.tf32.tf32.f32 "
        "{%0,%1,%2,%3},{%4,%5,%6,%7},{%8,%9},{%0,%1,%2,%3};"
        : "+f"(d[0]), "+f"(d[1]), "+f"(d[2]), "+f"(d[3])
        : "r"(a0), "r"(a1), "r"(a2), "r"(a3), "r"(b0), "r"(b1));
}
__device__ __forceinline__ float ftanh(float v) {
    float e = __expf(2.0f * v);
    return 1.0f - __fdividef(2.0f, e + 1.0f);
}

__device__ __forceinline__ void stage_store(char* smem, int buf,
                                            const float4* pf, int rowb, int k4) {
    char* base = smem + SM_A + buf * A_BUF;
    #pragma unroll
    for (int i = 0; i < 4; ++i) {
        int row = rowb + 16 * i;
        float4 v = pf[i], hi, lo;
        hi.x = tf32_rna(v.x); lo.x = tf32_rna(v.x - hi.x);
        hi.y = tf32_rna(v.y); lo.y = tf32_rna(v.y - hi.y);
        hi.z = tf32_rna(v.z); lo.z = tf32_rna(v.z - hi.z);
        hi.w = tf32_rna(v.w); lo.w = tf32_rna(v.w - hi.w);
        int off = (row * 68 + k4 * 4) * 4;
        *(float4*)(base + off)           = hi;
        *(float4*)(base + A_PLANE + off) = lo;
    }
}

__global__ void __launch_bounds__(NTHR, 1)
rnn_kernel(const float* __restrict__ x,    const float* __restrict__ W_hx,
           const float* __restrict__ b_hx, const float* __restrict__ W_hh,
           const float* __restrict__ b_hh, const float* __restrict__ W_oh,
           const float* __restrict__ b_oh, float* __restrict__ out)
{
    extern __shared__ char smem[];
    float* xs  = (float*)(smem + SM_XS);
    float* wxs = (float*)(smem + SM_WX);
    float* bbs = (float*)(smem + SM_BB);

    const int tid = threadIdx.x, lane = tid & 31, wid = tid >> 5;
    const int cb = blockIdx.x, rb = blockIdx.y;
    const int row0 = rb * BM, col0 = cb * BN;

    // Build fragment-ready B (hi/lo tf32) once; resident for all 1024 steps.
    // slot i = kb*64 + np*32 + lane: float4 = (b0@nb=2np, b1@nb=2np, b0@nb=2np+1, b1@nb=2np+1)
    // b0 = W_hh[col0 + n][kb*8 + lane%4], b1 = same k+4, n = np*16 + lane/4 (+8 for second).
    for (int i = tid; i < 4096; i += NTHR) {
        int ln = i & 31, np = (i >> 5) & 1, kb = i >> 6;
        int k0 = kb * 8 + (ln & 3);
        const float* wr0 = W_hh + (col0 + np * 16 + (ln >> 2)) * H;
        const float* wr1 = wr0 + 8 * H;
        float w00 = wr0[k0], w01 = wr0[k0 + 4];
        float w10 = wr1[k0], w11 = wr1[k0 + 4];
        float4 hi, lo;
        hi.x = tf32_rna(w00); lo.x = tf32_rna(w00 - hi.x);
        hi.y = tf32_rna(w01); lo.y = tf32_rna(w01 - hi.y);
        hi.z = tf32_rna(w10); lo.z = tf32_rna(w10 - hi.z);
        hi.w = tf32_rna(w11); lo.w = tf32_rna(w11 - hi.w);
        *(float4*)(smem + SM_B + i * 16)           = hi;
        *(float4*)(smem + SM_B + B_PLANE + i * 16) = lo;
    }
    if (tid < BN) {
        wxs[tid] = W_hx[col0 + tid];
        bbs[tid] = b_hx[col0 + tid] + b_hh[col0 + tid];
    }
    {   // h0 = zeros; each CTA zeroes a disjoint 1/128 slice
        int cta = rb * CBX + cb;
        for (int i = tid; i < 2048; i += NTHR) g_h[0][cta * 2048 + i] = 0.0f;
    }
    grid_barrier(1u);

    const int k4 = tid & 15, rowb = tid >> 4;     // staging roles
    // compute: warp wid owns k8-block (c*8 + wid) of each chunk
    const int aoff0 = (((lane >> 2) * 68 + wid * 8 + (lane & 3)) * 4);

    for (int t = 0; t < S; ++t) {
        const float* hin  = g_h[t & 1];
        float*       hout = g_h[(t + 1) & 1];
        if (tid < BM) xs[tid] = x[(row0 + tid) * S + t];

        float D[4][4][4];
        #pragma unroll
        for (int rg = 0; rg < 4; ++rg)
            #pragma unroll
            for (int nb = 0; nb < 4; ++nb)
                #pragma unroll
                for (int r = 0; r < 4; ++r) D[rg][nb][r] = 0.0f;

        const float* hbase = hin + (row0 + rowb) * H + k4 * 4;
        float4 pf[4];
        #pragma unroll
        for (int i = 0; i < 4; ++i) pf[i] = *(const float4*)(hbase + i * 16 * H);
        stage_store(smem, 0, pf, rowb, k4);

        #pragma unroll
        for (int c = 0; c < NCH; ++c) {
            __syncthreads();                       // chunk c visible; buf (c+1)&1 free
            if (c + 1 < NCH) {
                #pragma unroll
                for (int i = 0; i < 4; ++i)
                    pf[i] = *(const float4*)(hbase + (c + 1) * 64 + i * 16 * H);
            }
            // B fragments for this warp's k8-block
            const char* bb_ = smem + SM_B + (size_t)((c * 8 + wid) * 2) * 512 + lane * 16;
            float4 bh0 = *(const float4*)(bb_);
            float4 bh1 = *(const float4*)(bb_ + 512);
            float4 bl0 = *(const float4*)(bb_ + B_PLANE);
            float4 bl1 = *(const float4*)(bb_ + B_PLANE + 512);
            uint32_t bh[8] = { fu(bh0.x), fu(bh0.y), fu(bh0.z), fu(bh0.w),
                               fu(bh1.x), fu(bh1.y), fu(bh1.z), fu(bh1.w) };
            uint32_t bl[8] = { fu(bl0.x), fu(bl0.y), fu(bl0.z), fu(bl0.w),
                               fu(bl1.x), fu(bl1.y), fu(bl1.z), fu(bl1.w) };
            const char* abase = smem + SM_A + (c & 1) * A_BUF + aoff0;
            #pragma unroll
            for (int rg = 0; rg < 4; ++rg) {
                const char* ar = abase + rg * (16 * 68 * 4);
                uint32_t ah0 = *(const uint32_t*)(ar);
                uint32_t ah1 = *(const uint32_t*)(ar + 8 * 68 * 4);
                uint32_t ah2 = *(const uint32_t*)(ar + 16);
                uint32_t ah3 = *(const uint32_t*)(ar + 8 * 68 * 4 + 16);
                uint32_t al0 = *(const uint32_t*)(ar + A_PLANE);
                uint32_t al1 = *(const uint32_t*)(ar + A_PLANE + 8 * 68 * 4);
                uint32_t al2 = *(const uint32_t*)(ar + A_PLANE + 16);
                uint32_t al3 = *(const uint32_t*)(ar + A_PLANE + 8 * 68 * 4 + 16);
                #pragma unroll
                for (int nb = 0; nb < 4; ++nb) {
                    mma8(D[rg][nb], ah0, ah1, ah2, ah3, bh[2*nb], bh[2*nb+1]);
                    mma8(D[rg][nb], al0, al1, al2, al3, bh[2*nb], bh[2*nb+1]);
                    mma8(D[rg][nb], ah0, ah1, ah2, ah3, bl[2*nb], bl[2*nb+1]);
                }
            }
            if (c + 1 < NCH) stage_store(smem, (c + 1) & 1, pf, rowb, k4);
        }
        __syncthreads();                           // compute done; A region reusable

        // cross-warp reduction scratch (aliases A buffers): scr[w*512 + rg*128 + nb*32 + lane]
        float4* scr = (float4*)(smem + SM_A);
        #pragma unroll
        for (int rg = 0; rg < 4; ++rg)
            #pragma unroll
            for (int nb = 0; nb < 4; ++nb)
                scr[(wid * 512) + rg * 128 + nb * 32 + lane] =
                    make_float4(D[rg][nb][0], D[rg][nb][1], D[rg][nb][2], D[rg][nb][3]);
        __syncthreads();

        #pragma unroll
        for (int sidx = 0; sidx < 2; ++sidx) {
            int s = tid + sidx * 256;
            float4 v = scr[s];
            #pragma unroll
            for (int w = 1; w < 8; ++w) {
                float4 p = scr[w * 512 + s];
                v.x += p.x; v.y += p.y; v.z += p.z; v.w += p.w;
            }
            int ln = s & 31, nb = (s >> 5) & 3, rg = s >> 7;
            int r1 = rg * 16 + (ln >> 2);
            int jc = nb * 8 + 2 * (ln & 3);
            float xv1 = xs[r1], xv2 = xs[r1 + 8];
            float wj0 = wxs[jc], wj1 = wxs[jc + 1];
            float bj0 = bbs[jc], bj1 = bbs[jc + 1];
            float2 o1, o2;
            o1.x = ftanh(fmaf(xv1, wj0, v.x) + bj0);
            o1.y = ftanh(fmaf(xv1, wj1, v.y) + bj1);
            o2.x = ftanh(fmaf(xv2, wj0, v.z) + bj0);
            o2.y = ftanh(fmaf(xv2, wj1, v.w) + bj1);
            *(float2*)(hout + (row0 + r1) * H + col0 + jc)     = o1;
            *(float2*)(hout + (row0 + r1 + 8) * H + col0 + jc) = o2;
        }
        grid_barrier(t == S - 1 ? 0u : (unsigned)(t + 2));
    }

    // Final projection + softmax: cb==0 CTAs handle their 64 rows. h final in g_h[0].
    if (cb == 0) {
        float* wo = (float*)(smem + SM_A);                 // 5120 floats
        for (int i = tid; i < OUTD * H; i += NTHR) wo[i] = W_oh[i];
        __syncthreads();
        const float* hf = g_h[0];
        int r = tid >> 2, q = tid & 3;                     // 4 threads/row, 128 k each
        float p[OUTD];
        #pragma unroll
        for (int od = 0; od < OUTD; ++od) p[od] = 0.f;
        const float* hr = hf + (row0 + r) * H + q * 128;
        for (int k = 0; k < 128; k += 4) {
            float4 hv = *(const float4*)(hr + k);
            #pragma unroll
            for (int od = 0; od < OUTD; ++od) {
                const float* wr = wo + od * H + q * 128 + k;
                p[od] += hv.x * wr[0] + hv.y * wr[1] + hv.z * wr[2] + hv.w * wr[3];
            }
        }
        float* pr = (float*)(smem + SM_A + 20480);         // 256 x 10 partials
        #pragma unroll
        for (int od = 0; od < OUTD; ++od) pr[tid * OUTD + od] = p[od];
        __syncthreads();
        if (tid < BM) {
            float o[OUTD];
            #pragma unroll
            for (int od = 0; od < OUTD; ++od)
                o[od] = pr[(4 * tid) * OUTD + od] + pr[(4 * tid + 1) * OUTD + od]
                      + pr[(4 * tid + 2) * OUTD + od] + pr[(4 * tid + 3) * OUTD + od]
                      + b_oh[od];
            float mx = o[0];
            #pragma unroll
            for (int od = 1; od < OUTD; ++od) mx = fmaxf(mx, o[od]);
            float ssum = 0.f;
            #pragma unroll
            for (int od = 0; od < OUTD; ++od) { o[od] = expf(o[od] - mx); ssum += o[od]; }
            float inv = 1.0f / ssum;
            #pragma unroll
            for (int od = 0; od < OUTD; ++od)
                out[(row0 + tid) * OUTD + od] = o[od] * inv;
        }
    }
}

extern "C" void kernel_launch(void* const* d_in, const int* in_sizes, int n_in,
                              void* d_out, int out_size) {
    const float* x    = (const float*)d_in[0];
    const float* W_hx = (const float*)d_in[1];
    const float* b_hx = (const float*)d_in[2];
    const float* W_hh = (const float*)d_in[3];
    const float* b_hh = (const float*)d_in[4];
    const float* W_oh = (const float*)d_in[5];
    const float* b_oh = (const float*)d_in[6];
    float* out = (float*)d_out;

    cudaFuncSetAttribute(rnn_kernel, cudaFuncAttributeMaxDynamicSharedMemorySize, SMEM_BYTES);
    rnn_kernel<<<dim3(CBX, RBY, 1), NTHR, SMEM_BYTES>>>(x, W_hx, b_hx, W_hh, b_hh, W_oh, b_oh, out);
}

// round 11
// speedup vs baseline: 1.4545x; 1.0897x over previous
#include <cuda_runtime.h>
#include <math.h>
#include <stdint.h>

// VanillaRNN persistent kernel, v6: mma.sync TF32 3-product split, reshaped.
// 128 CTAs, CTA tile 64(batch) x 32(cols), K=512.
// 16 warps: k-split 8 x m-split 2 -> 32 accumulators/thread (no spills).
// A staged fp32 (single plane); hi/lo tf32 split in registers at frag load.
// B (W_hh) fragment-ready hi/lo, resident in smem all 1024 steps.

#define CBX 16     // column blocks (512/32)
#define RBY 8      // row blocks    (512/64)
#define NCTA (CBX*RBY)
#define NTHR 512

constexpr int S = 1024, H = 512, OUTD = 10;
constexpr int BM = 64, BN = 32;
constexpr int NCH = 8;                        // 512/64 k-chunks

// smem byte offsets
constexpr int SM_XS = 0;                      // 64 floats x[:,t]
constexpr int SM_WX = 256;                    // 32 floats W_hx
constexpr int SM_BB = 384;                    // 32 floats b_hx+b_hh
constexpr int SM_A  = 1024;                   // A fp32: [2 buf][64 rows][68]
constexpr int A_BUF = 64 * 68 * 4;            // 17408 B
constexpr int SM_B  = SM_A + 2 * A_BUF;       // 35840
constexpr int B_PLANE = 64 * 2 * 32 * 16;     // 65536 B
constexpr int SM_RED2 = SM_B + 2 * B_PLANE;   // 166912 (mg=1 scratch, 32 KB)
constexpr int SMEM_BYTES = SM_RED2 + 32768;   // 199680 B

__device__ __align__(16) float g_h[2][H * H]; // ping-pong hidden state (row-major)
__device__ unsigned g_arrive = 0;
__device__ unsigned g_phase  = 0;

__device__ __forceinline__ void grid_barrier(unsigned v) {
    __syncthreads();
    if (threadIdx.x == 0) {
        __threadfence();
        unsigned prev = atomicAdd(&g_arrive, 1u);
        if (prev == (unsigned)(NCTA - 1)) {
            *(volatile unsigned*)&g_arrive = 0u;
            __threadfence();
            *(volatile unsigned*)&g_phase = v;
        } else {
            while (*(volatile unsigned*)&g_phase != v) { }
        }
        __threadfence();
    }
    __syncthreads();
}

__device__ __forceinline__ float tf32_rna(float v) {
    float r; asm("cvt.rna.tf32.f32 %0, %1;" : "=f"(r) : "f"(v)); return r;
}
__device__ __forceinline__ uint32_t fu(float v) { return __float_as_uint(v); }

__device__ __forceinline__ void mma8(float d[4], uint32_t a0, uint32_t a1,
                                     uint32_t a2, uint32_t a3,
                                     uint32_t b0, uint32_t b1) {
    asm volatile(
        "mma.sync.aligned.m16n8k8.row.col.f32.tf32.tf32.f32 "
        "{%0,%1,%2,%3},{%4,%5,%6,%7},{%8,%9},{%0,%1,%2,%3};"
        : "+f"(d[0]), "+f"(d[1]), "+f"(d[2]), "+f"(d[3])
        : "r"(a0), "r"(a1), "r"(a2), "r"(a3), "r"(b0), "r"(b1));
}
__device__ __forceinline__ float ftanh(float v) {
    float e = __expf(2.0f * v);
    return 1.0f - __fdividef(2.0f, e + 1.0f);
}

__global__ void __launch_bounds__(NTHR, 1)
rnn_kernel(const float* __restrict__ x,    const float* __restrict__ W_hx,
           const float* __restrict__ b_hx, const float* __restrict__ W_hh,
           const float* __restrict__ b_hh, const float* __restrict__ W_oh,
           const float* __restrict__ b_oh, float* __restrict__ out)
{
    extern __shared__ char smem[];
    float* xs  = (float*)(smem + SM_XS);
    float* wxs = (float*)(smem + SM_WX);
    float* bbs = (float*)(smem + SM_BB);

    const int tid = threadIdx.x, lane = tid & 31, wid = tid >> 5;
    const int cb = blockIdx.x, rb = blockIdx.y;
    const int row0 = rb * BM, col0 = cb * BN;
    const int kg = wid & 7;                 // k-group: k8 block (c*8 + kg)
    const int mg = wid >> 3;                // m-half: rows [mg*32, mg*32+32)

    // Build fragment-ready B (hi/lo tf32) once; resident for all 1024 steps.
    // slot i = kb*64 + np*32 + lane: float4 = (b0@n8=2np, b1@2np, b0@2np+1, b1@2np+1)
    for (int i = tid; i < 4096; i += NTHR) {
        int ln = i & 31, np = (i >> 5) & 1, kb = i >> 6;
        int k0 = kb * 8 + (ln & 3);
        const float* wr0 = W_hh + (col0 + np * 16 + (ln >> 2)) * H;
        const float* wr1 = wr0 + 8 * H;
        float w00 = wr0[k0], w01 = wr0[k0 + 4];
        float w10 = wr1[k0], w11 = wr1[k0 + 4];
        float4 hi, lo;
        hi.x = tf32_rna(w00); lo.x = tf32_rna(w00 - hi.x);
        hi.y = tf32_rna(w01); lo.y = tf32_rna(w01 - hi.y);
        hi.z = tf32_rna(w10); lo.z = tf32_rna(w10 - hi.z);
        hi.w = tf32_rna(w11); lo.w = tf32_rna(w11 - hi.w);
        *(float4*)(smem + SM_B + i * 16)           = hi;
        *(float4*)(smem + SM_B + B_PLANE + i * 16) = lo;
    }
    if (tid < BN) {
        wxs[tid] = W_hx[col0 + tid];
        bbs[tid] = b_hx[col0 + tid] + b_hh[col0 + tid];
    }
    {   // h0 = zeros; each CTA zeroes a disjoint 1/128 slice
        int cta = rb * CBX + cb;
        for (int i = tid; i < 2048; i += NTHR) g_h[0][cta * 2048 + i] = 0.0f;
    }
    grid_barrier(1u);

    // staging roles: thread stores rows srow and srow+32, k-float4 sfc of each chunk
    const int srow = tid >> 4, sfc = tid & 15;
    // fragment address (words): row mg*32+lane/4 (+rg*16,+8), k kg*8+lane%4 (+4)
    const int aoff = ((mg * 32 + (lane >> 2)) * 68 + kg * 8 + (lane & 3)) * 4;

    for (int t = 0; t < S; ++t) {
        const float* hin  = g_h[t & 1];
        float*       hout = g_h[(t + 1) & 1];
        if (tid < BM) xs[tid] = x[(row0 + tid) * S + t];

        float D[2][4][4];
        #pragma unroll
        for (int rg = 0; rg < 2; ++rg)
            #pragma unroll
            for (int nb = 0; nb < 4; ++nb)
                #pragma unroll
                for (int r = 0; r < 4; ++r) D[rg][nb][r] = 0.0f;

        const float* hp0 = hin + (row0 + srow) * H + sfc * 4;
        const float* hp1 = hp0 + 32 * H;
        float4 pa = *(const float4*)hp0;
        float4 pb = *(const float4*)hp1;
        {   // stage chunk 0 (fp32, single plane)
            char* bufp = smem + SM_A;
            *(float4*)(bufp + (srow * 68 + sfc * 4) * 4)        = pa;
            *(float4*)(bufp + ((srow + 32) * 68 + sfc * 4) * 4) = pb;
        }

        #pragma unroll 2
        for (int c = 0; c < NCH; ++c) {
            __syncthreads();                   // chunk c visible; buf (c+1)&1 free
            if (c + 1 < NCH) {
                pa = *(const float4*)(hp0 + (c + 1) * 64);
                pb = *(const float4*)(hp1 + (c + 1) * 64);
            }
            // B fragments for this warp's k8 block (kb = c*8 + kg)
            const char* bbp = smem + SM_B + (size_t)(c * 8 + kg) * 1024 + lane * 16;
            float4 bh0 = *(const float4*)(bbp);
            float4 bh1 = *(const float4*)(bbp + 512);
            float4 bl0 = *(const float4*)(bbp + B_PLANE);
            float4 bl1 = *(const float4*)(bbp + B_PLANE + 512);
            uint32_t BH[8] = { fu(bh0.x), fu(bh0.y), fu(bh0.z), fu(bh0.w),
                               fu(bh1.x), fu(bh1.y), fu(bh1.z), fu(bh1.w) };
            uint32_t BL[8] = { fu(bl0.x), fu(bl0.y), fu(bl0.z), fu(bl0.w),
                               fu(bl1.x), fu(bl1.y), fu(bl1.z), fu(bl1.w) };
            const char* ab = smem + SM_A + (c & 1) * A_BUF + aoff;
            #pragma unroll
            for (int rg = 0; rg < 2; ++rg) {
                const char* ar = ab + rg * (16 * 68 * 4);
                float f0 = *(const float*)(ar);
                float f1 = *(const float*)(ar + 8 * 68 * 4);
                float f2 = *(const float*)(ar + 16);
                float f3 = *(const float*)(ar + 8 * 68 * 4 + 16);
                float h0 = tf32_rna(f0), h1 = tf32_rna(f1);
                float h2 = tf32_rna(f2), h3 = tf32_rna(f3);
                uint32_t ah0 = fu(h0), ah1 = fu(h1), ah2 = fu(h2), ah3 = fu(h3);
                uint32_t al0 = fu(tf32_rna(f0 - h0)), al1 = fu(tf32_rna(f1 - h1));
                uint32_t al2 = fu(tf32_rna(f2 - h2)), al3 = fu(tf32_rna(f3 - h3));
                #pragma unroll
                for (int nb = 0; nb < 4; ++nb) {
                    mma8(D[rg][nb], ah0, ah1, ah2, ah3, BH[2*nb], BH[2*nb+1]);
                    mma8(D[rg][nb], al0, al1, al2, al3, BH[2*nb], BH[2*nb+1]);
                    mma8(D[rg][nb], ah0, ah1, ah2, ah3, BL[2*nb], BL[2*nb+1]);
                }
            }
            if (c + 1 < NCH) {
                char* bufp = smem + SM_A + ((c + 1) & 1) * A_BUF;
                *(float4*)(bufp + (srow * 68 + sfc * 4) * 4)        = pa;
                *(float4*)(bufp + ((srow + 32) * 68 + sfc * 4) * 4) = pb;
            }
        }
        __syncthreads();                       // compute done; A region reusable

        // k-partials: mg=0 warps -> A-region scratch, mg=1 warps -> dedicated scratch
        {
            float4* scr = (float4*)(smem + (mg ? SM_RED2 : SM_A));
            #pragma unroll
            for (int rg = 0; rg < 2; ++rg)
                #pragma unroll
                for (int nb = 0; nb < 4; ++nb)
                    scr[kg * 256 + rg * 128 + nb * 32 + lane] =
                        make_float4(D[rg][nb][0], D[rg][nb][1],
                                    D[rg][nb][2], D[rg][nb][3]);
        }
        __syncthreads();

        // Reduce 8 k-partials + epilogue: each thread finishes 4 outputs.
        {
            int mgp = tid >> 8, idx = tid & 255;
            const float4* scr = (const float4*)(smem + (mgp ? SM_RED2 : SM_A));
            float4 v = scr[idx];
            #pragma unroll
            for (int k2 = 1; k2 < 8; ++k2) {
                float4 p = scr[k2 * 256 + idx];
                v.x += p.x; v.y += p.y; v.z += p.z; v.w += p.w;
            }
            int rg = idx >> 7, nb = (idx >> 5) & 3, ln = idx & 31;
            int r1 = mgp * 32 + rg * 16 + (ln >> 2);
            int jc = nb * 8 + 2 * (ln & 3);
            float xv1 = xs[r1], xv2 = xs[r1 + 8];
            float wj0 = wxs[jc], wj1 = wxs[jc + 1];
            float bj0 = bbs[jc], bj1 = bbs[jc + 1];
            float2 o1, o2;
            o1.x = ftanh(fmaf(xv1, wj0, v.x) + bj0);
            o1.y = ftanh(fmaf(xv1, wj1, v.y) + bj1);
            o2.x = ftanh(fmaf(xv2, wj0, v.z) + bj0);
            o2.y = ftanh(fmaf(xv2, wj1, v.w) + bj1);
            *(float2*)(hout + (row0 + r1) * H + col0 + jc)     = o1;
            *(float2*)(hout + (row0 + r1 + 8) * H + col0 + jc) = o2;
        }
        grid_barrier(t == S - 1 ? 0u : (unsigned)(t + 2));
    }

    // Final projection + softmax: cb==0 CTAs handle their 64 rows. h final in g_h[0].
    if (cb == 0) {
        float* wo = (float*)(smem + SM_A);              // 5120 floats
        for (int i = tid; i < OUTD * H; i += NTHR) wo[i] = W_oh[i];
        __syncthreads();
        const float* hf = g_h[0];
        int r = tid >> 3, q = tid & 7;                  // 8 threads/row, 64 k each
        float p[OUTD];
        #pragma unroll
        for (int od = 0; od < OUTD; ++od) p[od] = 0.f;
        const float* hr = hf + (row0 + r) * H + q * 64;
        for (int k = 0; k < 64; k += 4) {
            float4 hv = *(const float4*)(hr + k);
            #pragma unroll
            for (int od = 0; od < OUTD; ++od) {
                const float* wr = wo + od * H + q * 64 + k;
                p[od] += hv.x * wr[0] + hv.y * wr[1] + hv.z * wr[2] + hv.w * wr[3];
            }
        }
        float* pr = (float*)(smem + SM_A + 20480);      // 512 x 10 partials
        #pragma unroll
        for (int od = 0; od < OUTD; ++od) pr[tid * OUTD + od] = p[od];
        __syncthreads();
        if (tid < BM) {
            float o[OUTD];
            #pragma unroll
            for (int od = 0; od < OUTD; ++od) {
                float s0 = 0.f;
                #pragma unroll
                for (int j = 0; j < 8; ++j)
                    s0 += pr[(8 * tid + j) * OUTD + od];
                o[od] = s0 + b_oh[od];
            }
            float mx = o[0];
            #pragma unroll
            for (int od = 1; od < OUTD; ++od) mx = fmaxf(mx, o[od]);
            float ssum = 0.f;
            #pragma unroll
            for (int od = 0; od < OUTD; ++od) { o[od] = expf(o[od] - mx); ssum += o[od]; }
            float inv = 1.0f / ssum;
            #pragma unroll
            for (int od = 0; od < OUTD; ++od)
                out[(row0 + tid) * OUTD + od] = o[od] * inv;
        }
    }
}

extern "C" void kernel_launch(void* const* d_in, const int* in_sizes, int n_in,
                              void* d_out, int out_size) {
    const float* x    = (const float*)d_in[0];
    const float* W_hx = (const float*)d_in[1];
    const float* b_hx = (const float*)d_in[2];
    const float* W_hh = (const float*)d_in[3];
    const float* b_hh = (const float*)d_in[4];
    const float* W_oh = (const float*)d_in[5];
    const float* b_oh = (const float*)d_in[6];
    float* out = (float*)d_out;

    cudaFuncSetAttribute(rnn_kernel, cudaFuncAttributeMaxDynamicSharedMemorySize, SMEM_BYTES);
    rnn_kernel<<<dim3(CBX, RBY, 1), NTHR, SMEM_BYTES>>>(x, W_hx, b_hx, W_hh, b_hh, W_oh, b_oh, out);
}